// round 5
// baseline (speedup 1.0000x reference)
#include <cuda_runtime.h>
#include <cuda_bf16.h>

#define NN 8192
#define NV4 (NN / 4)                  // float4 per row = 2048
#define TOTV4 (NN * (NN / 4))         // total float4 = 16,777,216 = 2^24
#define BLOCKS 1216                   // 8 CTAs/SM x 152 SMs (GB300) = one balanced wave
#define THREADS 256
#define STRIDE (BLOCKS * THREADS)     // 311,296

__device__ double g_acc;              // statically zero-initialized
__device__ float  g_betas2[NN];       // betas * log2(e)

#define LOG2E 1.4426950408889634f
#define LN2   0.6931471805599453f

// softplus in log2 domain: y = (beta_j - beta_i) * log2(e)
// sp2(y) = max(y,0) + log2(1 + 2^(-|y|));  softplus = ln2 * sp2
__device__ __forceinline__ float sp2(float y) {
    float e = exp2f(-fabsf(y));       // MUFU EX2
    float l = __log2f(1.0f + e);      // MUFU LG2
    return fmaxf(y, 0.0f) + l;
}

__global__ void bt_prescale_kernel(const float* __restrict__ betas) {
    int i = blockIdx.x * blockDim.x + threadIdx.x;
    if (i < NN) g_betas2[i] = betas[i] * LOG2E;
}

__global__ void __launch_bounds__(THREADS)
bt_main_kernel(const float4* __restrict__ W) {
    const float4* __restrict__ B4 = reinterpret_cast<const float4*>(g_betas2);

    float local = 0.0f;
    int idx = blockIdx.x * THREADS + threadIdx.x;

    #pragma unroll 8
    for (int v = idx; v < TOTV4; v += STRIDE) {
        int row  = v >> 11;           // v / 2048
        int colv = v & (NV4 - 1);     // v % 2048

        float  bi = g_betas2[row];    // L1-resident (32 KB)
        float4 w  = __ldcs(&W[v]);    // streaming read-once: evict-first
        float4 bj = B4[colv];         // L1-resident

        // unconditional, including diagonal (corrected by bt_diag_kernel)
        float t0 = w.x * sp2(bj.x - bi);
        float t1 = w.y * sp2(bj.y - bi);
        float t2 = w.z * sp2(bj.z - bi);
        float t3 = w.w * sp2(bj.w - bi);

        local += (t0 + t1) + (t2 + t3);
    }

    // warp reduce
    #pragma unroll
    for (int off = 16; off > 0; off >>= 1)
        local += __shfl_down_sync(0xFFFFFFFFu, local, off);

    // block reduce via shared
    __shared__ float warp_sums[8];
    int lane = threadIdx.x & 31;
    int wid  = threadIdx.x >> 5;
    if (lane == 0) warp_sums[wid] = local;
    __syncthreads();

    if (wid == 0) {
        float s = (lane < (THREADS >> 5)) ? warp_sums[lane] : 0.0f;
        #pragma unroll
        for (int off = 4; off > 0; off >>= 1)
            s += __shfl_down_sync(0xFFFFFFFFu, s, off);
        if (lane == 0)
            atomicAdd(&g_acc, (double)s);
    }
}

// subtract diagonal: in log2 domain sp2(0) = 1, so subtract sum_i W[i,i]
__global__ void __launch_bounds__(THREADS)
bt_diag_kernel(const float* __restrict__ W) {
    int i = blockIdx.x * blockDim.x + threadIdx.x;   // 32 blocks x 256 = 8192
    float d = -W[(size_t)i * (NN + 1)];

    #pragma unroll
    for (int off = 16; off > 0; off >>= 1)
        d += __shfl_down_sync(0xFFFFFFFFu, d, off);

    __shared__ float warp_sums[8];
    int lane = threadIdx.x & 31;
    int wid  = threadIdx.x >> 5;
    if (lane == 0) warp_sums[wid] = d;
    __syncthreads();

    if (wid == 0) {
        float s = (lane < 8) ? warp_sums[lane] : 0.0f;
        #pragma unroll
        for (int off = 4; off > 0; off >>= 1)
            s += __shfl_down_sync(0xFFFFFFFFu, s, off);
        if (lane == 0)
            atomicAdd(&g_acc, (double)s);
    }
}

__global__ void bt_final_kernel(float* out) {
    out[0] = (float)(g_acc * (double)LN2);
    g_acc  = 0.0;   // reset for next graph replay (stream-ordered)
}

extern "C" void kernel_launch(void* const* d_in, const int* in_sizes, int n_in,
                              void* d_out, int out_size) {
    const float* W     = (const float*)d_in[0];   // win_matrix [N,N] fp32
    const float* betas = (const float*)d_in[1];   // betas [N] fp32
    float* out = (float*)d_out;

    bt_prescale_kernel<<<(NN + THREADS - 1) / THREADS, THREADS>>>(betas);
    bt_main_kernel<<<BLOCKS, THREADS>>>((const float4*)W);
    bt_diag_kernel<<<NN / THREADS, THREADS>>>(W);
    bt_final_kernel<<<1, 1>>>(out);
}